// round 17
// baseline (speedup 1.0000x reference)
#include <cuda_runtime.h>
#include <cuda_bf16.h>
#include <cuda_fp16.h>
#include <math.h>

// ---------------- constants ----------------
#define BB   32
#define LL   1024
#define DD   512
#define NH   8
#define HE   64
#define DFF  2048
#define CIN  7
#define MK   4
#define MROWS (BB*LL)          // 32768
#define BLD  (BB*LL*DD)        // 16777216
#define BL7  (BB*LL*CIN)       // 229376
#define TOPK 6

typedef __nv_bfloat16 bf16;
typedef __half hf;

// ---------------- device scratch ----------------
__device__ float g_A   [BLD];
__device__ float g_Bf  [BLD];
__device__ float g_v   [BLD];
__device__ float g_enc [BLD];
__device__ float g_t123[BLD];
__device__ float g_G   [(size_t)BB*LL*LL];   // Gram matrices (134 MB)
__device__ float g_cp  [BB*32*LL];           // diagonal partial sums
__device__ float g_cm  [BB*DD];
__device__ float g_w   [BB*8];
__device__ int   g_dly [BB*8];
__device__ float g_sx  [BL7];
__device__ float g_tx  [BL7];
__device__ float g_seas[BL7];
__device__ float g_trd [BL7];
__device__ float g_menc[BB*CIN];
// fused V weights (4 attentions)
__device__ float g_wvo4[4*DD*DD];     // Wv @ Wo
__device__ float g_bvo4[4*DD];        // bv@Wo + bo
// bf16 split buffers (Q/K path)
__device__ bf16 g_mh [8*DD*DD];       // splits: Wq^T[0..3], Wk^T[4..7]
__device__ bf16 g_ml [8*DD*DD];
__device__ bf16 g_s1h[MROWS*DD];
__device__ bf16 g_s1l[MROWS*DD];
__device__ bf16 g_ench[MROWS*DD];
__device__ bf16 g_encl[MROWS*DD];
__device__ bf16 g_qh [MROWS*DD];
__device__ bf16 g_ql [MROWS*DD];
__device__ bf16 g_kh [MROWS*DD];
__device__ bf16 g_kl [MROWS*DD];
// fp16 path (V*Wo + FF)
__device__ hf g_vh [4*DD*DD];
__device__ hf g_vl [4*DD*DD];
__device__ hf g_f1h[3*DD*DFF];
__device__ hf g_f1l[3*DD*DFF];
__device__ hf g_f2h[3*DFF*DD];
__device__ hf g_f2l[3*DFF*DD];
__device__ hf g_x1f[MROWS*DD];
__device__ hf g_ecf[MROWS*DD];
__device__ hf g_x2f[MROWS*DFF];

struct P4 { const float* p[4]; };
struct P3 { const float* p[3]; };

// ---------------- helpers ----------------
__device__ __forceinline__ void bsplit(float x, bf16& h, bf16& l){
    h = __float2bfloat16(x);
    l = __float2bfloat16(x - __bfloat162float(h));
}
__device__ __forceinline__ void hsplit(float x, hf& h, hf& l){
    h = __float2half(x);
    l = __float2half(x - __half2float(h));
}
__device__ __forceinline__ unsigned su32(const void* p){
    return (unsigned)__cvta_generic_to_shared(p);
}
__device__ __forceinline__ void cpa16(unsigned dst, const void* src){
    asm volatile("cp.async.cg.shared.global [%0], [%1], 16;" :: "r"(dst), "l"(src));
}
__device__ __forceinline__ void cpa_commit(){
    asm volatile("cp.async.commit_group;" ::: "memory");
}
__device__ __forceinline__ void cpa_wait2(){
    asm volatile("cp.async.wait_group 2;" ::: "memory");
}
__device__ __forceinline__ void ldsm4(unsigned* r, unsigned addr){
    asm volatile("ldmatrix.sync.aligned.m8n8.x4.shared.b16 {%0,%1,%2,%3}, [%4];"
        : "=r"(r[0]), "=r"(r[1]), "=r"(r[2]), "=r"(r[3]) : "r"(addr));
}
__device__ __forceinline__ void mma16(float* d, const unsigned* a, unsigned b0, unsigned b1){
    asm volatile("mma.sync.aligned.m16n8k16.row.col.f32.bf16.bf16.f32 "
        "{%0,%1,%2,%3},{%4,%5,%6,%7},{%8,%9},{%0,%1,%2,%3};"
        : "+f"(d[0]), "+f"(d[1]), "+f"(d[2]), "+f"(d[3])
        : "r"(a[0]), "r"(a[1]), "r"(a[2]), "r"(a[3]), "r"(b0), "r"(b1));
}
__device__ __forceinline__ void mma16h(float* d, const unsigned* a, unsigned b0, unsigned b1){
    asm volatile("mma.sync.aligned.m16n8k16.row.col.f32.f16.f16.f32 "
        "{%0,%1,%2,%3},{%4,%5,%6,%7},{%8,%9},{%0,%1,%2,%3};"
        : "+f"(d[0]), "+f"(d[1]), "+f"(d[2]), "+f"(d[3])
        : "r"(a[0]), "r"(a[1]), "r"(a[2]), "r"(a[3]), "r"(b0), "r"(b1));
}

// ---------------- split-bf16 mma.sync GEMM (Q/K path; 4-stage ring) ----------------
// Outputs bf16 splits Ch/Cl (+bias). N = DD.
#define RSTRIDE 80
#define AREA    10240
#define STAGEB  40960
#define NSTAGE  4
#define GEMM_SMEM (NSTAGE*STAGEB)   // 163840
__global__ void __launch_bounds__(512,1) gemm_mma_k(
    const bf16* __restrict__ Ahp, const bf16* __restrict__ Alp,
    const bf16* __restrict__ Bhp, const bf16* __restrict__ Blp,
    const float* __restrict__ bias,
    bf16* __restrict__ Ch, bf16* __restrict__ Cl, int K)
{
    extern __shared__ __align__(16) char dsm[];
    const int tid = threadIdx.x;
    const int lane = tid & 31, warp = tid >> 5;
    const int wm = warp >> 2, wn = warp & 3;
    const int bx = blockIdx.x, by = blockIdx.y;
    const int S = K >> 5;
    const unsigned sbase = su32(dsm);

    const int lrow = tid >> 2, lc16 = tid & 3;
    const bf16* gA_h = Ahp + (size_t)(by*128 + lrow)*K;
    const bf16* gA_l = Alp + (size_t)(by*128 + lrow)*K;
    const bf16* gB_h = Bhp + (size_t)(bx*128 + lrow)*K;
    const bf16* gB_l = Blp + (size_t)(bx*128 + lrow)*K;
    const unsigned sdst = lrow*RSTRIDE + lc16*16;

    float acc[2][4][4];
#pragma unroll
    for (int i=0;i<2;i++)
#pragma unroll
        for (int j=0;j<4;j++)
#pragma unroll
            for (int t=0;t<4;t++) acc[i][j][t]=0.f;

#pragma unroll
    for (int p=0;p<3;p++){
        if (p < S){
            unsigned b = sbase + p*STAGEB + sdst;
            int gk = p*32 + lc16*8;
            cpa16(b,            gA_h + gk);
            cpa16(b + AREA,     gA_l + gk);
            cpa16(b + 2*AREA,   gB_h + gk);
            cpa16(b + 3*AREA,   gB_l + gk);
        }
        cpa_commit();
    }

    const unsigned arow = (wm*32 + (lane & 15))*RSTRIDE + (lane >> 4)*16;
    const unsigned brow = (wn*32 + (lane & 15))*RSTRIDE + (lane >> 4)*16;

    for (int s=0; s<S; s++){
        cpa_wait2();
        __syncthreads();
        if (s+3 < S){
            unsigned b = sbase + ((s+3) & 3)*STAGEB + sdst;
            int gk = (s+3)*32 + lc16*8;
            cpa16(b,            gA_h + gk);
            cpa16(b + AREA,     gA_l + gk);
            cpa16(b + 2*AREA,   gB_h + gk);
            cpa16(b + 3*AREA,   gB_l + gk);
        }
        cpa_commit();
        const unsigned sb = sbase + (s & 3)*STAGEB;
#pragma unroll
        for (int k16=0; k16<2; k16++){
            const unsigned ko = k16*32;
            unsigned ah[8], al[8], bh[8], bl[8];
            ldsm4(ah,   sb + arow + ko);
            ldsm4(ah+4, sb + arow + ko + 16*RSTRIDE);
            ldsm4(al,   sb + AREA + arow + ko);
            ldsm4(al+4, sb + AREA + arow + ko + 16*RSTRIDE);
            ldsm4(bh,   sb + 2*AREA + brow + ko);
            ldsm4(bh+4, sb + 2*AREA + brow + ko + 16*RSTRIDE);
            ldsm4(bl,   sb + 3*AREA + brow + ko);
            ldsm4(bl+4, sb + 3*AREA + brow + ko + 16*RSTRIDE);
#pragma unroll
            for (int mf=0; mf<2; mf++){
#pragma unroll
                for (int nf=0; nf<4; nf++){
                    int g = (nf>>1)*4 + (nf&1);
                    mma16(acc[mf][nf], ah+mf*4, bh[g], bh[g+2]);
                    mma16(acc[mf][nf], ah+mf*4, bl[g], bl[g+2]);
                    mma16(acc[mf][nf], al+mf*4, bh[g], bh[g+2]);
                }
            }
        }
    }

#pragma unroll
    for (int mf=0; mf<2; mf++){
#pragma unroll
        for (int nf=0; nf<4; nf++){
            int r0  = by*128 + wm*32 + mf*16 + (lane>>2);
            int col = bx*128 + wn*32 + nf*8 + ((lane&3)<<1);
            float* d = acc[mf][nf];
#pragma unroll
            for (int h=0; h<2; h++){
                int r = r0 + h*8;
                size_t rowoff = (size_t)r * DD;
                float ox = d[2*h]   + __ldg(&bias[col]);
                float oy = d[2*h+1] + __ldg(&bias[col+1]);
                bf16 h0,l0,h1,l1;
                bsplit(ox,h0,l0); bsplit(oy,h1,l1);
                __nv_bfloat162 hv; hv.x=h0; hv.y=h1;
                __nv_bfloat162 lv; lv.x=l0; lv.y=l1;
                *(__nv_bfloat162*)&Ch[rowoff + col] = hv;
                *(__nv_bfloat162*)&Cl[rowoff + col] = lv;
            }
        }
    }
}

// ---------------- batched Gram GEMM: G[b] = Q[b] * K[b]^T (bf16 3-term) ----------------
__global__ void __launch_bounds__(512,1) corrg_k(
    const bf16* __restrict__ Qh, const bf16* __restrict__ Ql,
    const bf16* __restrict__ Kh, const bf16* __restrict__ Kl,
    float* __restrict__ G)
{
    extern __shared__ __align__(16) char dsm[];
    const int tid = threadIdx.x;
    const int lane = tid & 31, warp = tid >> 5;
    const int wm = warp >> 2, wn = warp & 3;
    const int bx = blockIdx.x, by = blockIdx.y, bz = blockIdx.z;
    const int S = DD >> 5;   // 16
    const unsigned sbase = su32(dsm);

    const int lrow = tid >> 2, lc16 = tid & 3;
    const bf16* gA_h = Qh + ((size_t)bz*LL + by*128 + lrow)*DD;
    const bf16* gA_l = Ql + ((size_t)bz*LL + by*128 + lrow)*DD;
    const bf16* gB_h = Kh + ((size_t)bz*LL + bx*128 + lrow)*DD;
    const bf16* gB_l = Kl + ((size_t)bz*LL + bx*128 + lrow)*DD;
    const unsigned sdst = lrow*RSTRIDE + lc16*16;

    float acc[2][4][4];
#pragma unroll
    for (int i=0;i<2;i++)
#pragma unroll
        for (int j=0;j<4;j++)
#pragma unroll
            for (int t=0;t<4;t++) acc[i][j][t]=0.f;

#pragma unroll
    for (int p=0;p<3;p++){
        if (p < S){
            unsigned b = sbase + p*STAGEB + sdst;
            int gk = p*32 + lc16*8;
            cpa16(b,            gA_h + gk);
            cpa16(b + AREA,     gA_l + gk);
            cpa16(b + 2*AREA,   gB_h + gk);
            cpa16(b + 3*AREA,   gB_l + gk);
        }
        cpa_commit();
    }

    const unsigned arow = (wm*32 + (lane & 15))*RSTRIDE + (lane >> 4)*16;
    const unsigned brow = (wn*32 + (lane & 15))*RSTRIDE + (lane >> 4)*16;

    for (int s=0; s<S; s++){
        cpa_wait2();
        __syncthreads();
        if (s+3 < S){
            unsigned b = sbase + ((s+3) & 3)*STAGEB + sdst;
            int gk = (s+3)*32 + lc16*8;
            cpa16(b,            gA_h + gk);
            cpa16(b + AREA,     gA_l + gk);
            cpa16(b + 2*AREA,   gB_h + gk);
            cpa16(b + 3*AREA,   gB_l + gk);
        }
        cpa_commit();
        const unsigned sb = sbase + (s & 3)*STAGEB;
#pragma unroll
        for (int k16=0; k16<2; k16++){
            const unsigned ko = k16*32;
            unsigned ah[8], al[8], bh[8], bl[8];
            ldsm4(ah,   sb + arow + ko);
            ldsm4(ah+4, sb + arow + ko + 16*RSTRIDE);
            ldsm4(al,   sb + AREA + arow + ko);
            ldsm4(al+4, sb + AREA + arow + ko + 16*RSTRIDE);
            ldsm4(bh,   sb + 2*AREA + brow + ko);
            ldsm4(bh+4, sb + 2*AREA + brow + ko + 16*RSTRIDE);
            ldsm4(bl,   sb + 3*AREA + brow + ko);
            ldsm4(bl+4, sb + 3*AREA + brow + ko + 16*RSTRIDE);
#pragma unroll
            for (int mf=0; mf<2; mf++){
#pragma unroll
                for (int nf=0; nf<4; nf++){
                    int g = (nf>>1)*4 + (nf&1);
                    mma16(acc[mf][nf], ah+mf*4, bh[g], bh[g+2]);
                    mma16(acc[mf][nf], ah+mf*4, bl[g], bl[g+2]);
                    mma16(acc[mf][nf], al+mf*4, bh[g], bh[g+2]);
                }
            }
        }
    }

#pragma unroll
    for (int mf=0; mf<2; mf++){
#pragma unroll
        for (int nf=0; nf<4; nf++){
            int r0  = by*128 + wm*32 + mf*16 + (lane>>2);
            int col = bx*128 + wn*32 + nf*8 + ((lane&3)<<1);
            float* d = acc[mf][nf];
#pragma unroll
            for (int h=0; h<2; h++){
                int r = r0 + h*8;
                size_t rowoff = ((size_t)bz*LL + r)*LL;
                *(float2*)&G[rowoff + col] = make_float2(d[2*h], d[2*h+1]);
            }
        }
    }
}

// ---------------- diagonal sums: Cp[b][chunk][tau] = sum over 32 rows of G[row][(row-tau)] ----------------
__global__ void diagsum_k(const float* __restrict__ G, float* __restrict__ Cp){
    int b = blockIdx.y, chunk = blockIdx.x, tid = threadIdx.x;
    const float* Gb = G + (size_t)b*LL*LL;
    int t0 = tid, t1 = tid+256, t2 = tid+512, t3 = tid+768;
    float a0=0.f, a1=0.f, a2=0.f, a3=0.f;
    for (int r0=0; r0<32; r0++){
        int row = chunk*32 + r0;
        const float* rp = Gb + (size_t)row*LL;
        a0 += __ldg(&rp[(row - t0) & 1023]);
        a1 += __ldg(&rp[(row - t1) & 1023]);
        a2 += __ldg(&rp[(row - t2) & 1023]);
        a3 += __ldg(&rp[(row - t3) & 1023]);
    }
    float* dst = Cp + ((size_t)b*32 + chunk)*LL;
    dst[t0]=a0; dst[t1]=a1; dst[t2]=a2; dst[t3]=a3;
}

// ---------------- partial-sum + top-6 + softmax ----------------
__global__ void corr_topk_k(const float* __restrict__ Cp, float* __restrict__ wout,
                            int* __restrict__ dout){
    __shared__ float corr[1024];
    __shared__ float rv[256];
    __shared__ int   ri[256];
    __shared__ float wv[TOPK];
    __shared__ int   dv[TOPK];
    int b = blockIdx.x, tid = threadIdx.x;
    for (int f=tid; f<1024; f+=256){
        float s=0.f;
        const float* p = Cp + (size_t)b*32*LL + f;
#pragma unroll
        for (int c=0;c<32;c++) s += p[(size_t)c*LL];
        corr[f] = s * (1.0f/512.0f);
    }
    __syncthreads();
    for (int it=0; it<TOPK; it++){
        float best = -1e30f; int bi = 1<<30;
        for (int f=tid;f<1024;f+=256){
            float v = corr[f];
            if (v > best || (v == best && f < bi)){ best = v; bi = f; }
        }
        rv[tid]=best; ri[tid]=bi; __syncthreads();
        for (int off=128; off; off>>=1){
            if (tid < off){
                if (rv[tid+off] > rv[tid] || (rv[tid+off]==rv[tid] && ri[tid+off]<ri[tid])){
                    rv[tid]=rv[tid+off]; ri[tid]=ri[tid+off];
                }
            }
            __syncthreads();
        }
        if (tid==0){ wv[it]=rv[0]; dv[it]=ri[0]; corr[ri[0]] = -1e30f; }
        __syncthreads();
    }
    if (tid==0){
        float mx = wv[0];
        float ex[TOPK]; float s=0.f;
        for (int i=0;i<TOPK;i++){ ex[i]=expf(wv[i]-mx); s+=ex[i]; }
        for (int i=0;i<TOPK;i++){ wout[b*8+i]=ex[i]/s; dout[b*8+i]=dv[i]; }
    }
}

// ---------------- fp16 2-term GEMM: C = A_fp16 * (Bh + Bl)^T ----------------
#define STAGE2B 30720
#define GEMM2_SMEM (NSTAGE*STAGE2B)  // 122880
__global__ void __launch_bounds__(512,1) gemm2h_k(
    const hf* __restrict__ Ap,
    const hf* __restrict__ Bhp, const hf* __restrict__ Blp,
    const float* __restrict__ bias, const float* __restrict__ res,
    float* __restrict__ C, hf* __restrict__ Cf,
    int N, int K, int dogelu)
{
    extern __shared__ __align__(16) char dsm[];
    const int tid = threadIdx.x;
    const int lane = tid & 31, warp = tid >> 5;
    const int wm = warp >> 2, wn = warp & 3;
    const int bx = blockIdx.x, by = blockIdx.y;
    const int S = K >> 5;
    const unsigned sbase = su32(dsm);

    const int lrow = tid >> 2, lc16 = tid & 3;
    const hf* gA   = Ap  + (size_t)(by*128 + lrow)*K;
    const hf* gB_h = Bhp + (size_t)(bx*128 + lrow)*K;
    const hf* gB_l = Blp + (size_t)(bx*128 + lrow)*K;
    const unsigned sdst = lrow*RSTRIDE + lc16*16;

    float acc[2][4][4];
#pragma unroll
    for (int i=0;i<2;i++)
#pragma unroll
        for (int j=0;j<4;j++)
#pragma unroll
            for (int t=0;t<4;t++) acc[i][j][t]=0.f;

#pragma unroll
    for (int p=0;p<3;p++){
        if (p < S){
            unsigned b = sbase + p*STAGE2B + sdst;
            int gk = p*32 + lc16*8;
            cpa16(b,            gA   + gk);
            cpa16(b + AREA,     gB_h + gk);
            cpa16(b + 2*AREA,   gB_l + gk);
        }
        cpa_commit();
    }

    const unsigned arow = (wm*32 + (lane & 15))*RSTRIDE + (lane >> 4)*16;
    const unsigned brow = (wn*32 + (lane & 15))*RSTRIDE + (lane >> 4)*16;

    for (int s=0; s<S; s++){
        cpa_wait2();
        __syncthreads();
        if (s+3 < S){
            unsigned b = sbase + ((s+3) & 3)*STAGE2B + sdst;
            int gk = (s+3)*32 + lc16*8;
            cpa16(b,            gA   + gk);
            cpa16(b + AREA,     gB_h + gk);
            cpa16(b + 2*AREA,   gB_l + gk);
        }
        cpa_commit();
        const unsigned sb = sbase + (s & 3)*STAGE2B;
#pragma unroll
        for (int k16=0; k16<2; k16++){
            const unsigned ko = k16*32;
            unsigned ah[8], bh[8], bl[8];
            ldsm4(ah,   sb + arow + ko);
            ldsm4(ah+4, sb + arow + ko + 16*RSTRIDE);
            ldsm4(bh,   sb + AREA + brow + ko);
            ldsm4(bh+4, sb + AREA + brow + ko + 16*RSTRIDE);
            ldsm4(bl,   sb + 2*AREA + brow + ko);
            ldsm4(bl+4, sb + 2*AREA + brow + ko + 16*RSTRIDE);
#pragma unroll
            for (int mf=0; mf<2; mf++){
#pragma unroll
                for (int nf=0; nf<4; nf++){
                    int g = (nf>>1)*4 + (nf&1);
                    mma16h(acc[mf][nf], ah+mf*4, bh[g], bh[g+2]);
                    mma16h(acc[mf][nf], ah+mf*4, bl[g], bl[g+2]);
                }
            }
        }
    }

#pragma unroll
    for (int mf=0; mf<2; mf++){
#pragma unroll
        for (int nf=0; nf<4; nf++){
            int r0  = by*128 + wm*32 + mf*16 + (lane>>2);
            int col = bx*128 + wn*32 + nf*8 + ((lane&3)<<1);
            float* d = acc[mf][nf];
#pragma unroll
            for (int h=0; h<2; h++){
                int r = r0 + h*8;
                size_t rowoff = (size_t)r * N;
                float2 o = make_float2(d[2*h], d[2*h+1]);
                if (bias){ o.x += __ldg(&bias[col]); o.y += __ldg(&bias[col+1]); }
                if (dogelu){
                    o.x = 0.5f*o.x*(1.0f+erff(o.x*0.7071067811865476f));
                    o.y = 0.5f*o.y*(1.0f+erff(o.y*0.7071067811865476f));
                }
                if (res){
                    float2 rr = *(const float2*)&res[rowoff + col];
                    o.x += rr.x; o.y += rr.y;
                }
                if (Cf){
                    __half2 hv; hv.x = __float2half(o.x); hv.y = __float2half(o.y);
                    *(__half2*)&Cf[rowoff + col] = hv;
                } else {
                    *(float2*)&C[rowoff + col] = o;
                }
            }
        }
    }
}

// ---------------- batched 512x512 matmuls: WVO[z] = Wv @ Wo ----------------
__global__ void mmvo_b_k(P4 wb, float* __restrict__ wvo){
    __shared__ float As[32][33], Bs[32][33];
    int z = blockIdx.z;
    const float* A = wb.p[z] + (size_t)2*DD*DD;
    const float* B = wb.p[z] + (size_t)3*DD*DD;
    float* C = wvo + (size_t)z*DD*DD;
    int i0 = blockIdx.y*32, j0 = blockIdx.x*32;
    int tx = threadIdx.x, ty = threadIdx.y;
    float acc[4] = {0.f,0.f,0.f,0.f};
    for (int k0=0;k0<512;k0+=32){
        for (int r=ty;r<32;r+=8){
            As[r][tx] = A[(size_t)(i0+r)*512 + k0+tx];
            Bs[r][tx] = B[(size_t)(k0+r)*512 + j0+tx];
        }
        __syncthreads();
#pragma unroll
        for (int k=0;k<32;k++){
            float bv = Bs[k][tx];
#pragma unroll
            for (int u=0;u<4;u++) acc[u] += As[ty+8*u][k]*bv;
        }
        __syncthreads();
    }
#pragma unroll
    for (int u=0;u<4;u++) C[(size_t)(i0+ty+8*u)*512 + j0+tx] = acc[u];
}

// ---------------- batched fused bias: bvo[z] = bv@Wo + bo ----------------
__global__ void biasvo_b_k(P4 bb, P4 wb, float* __restrict__ bvo){
    int z = blockIdx.y;
    int j = blockIdx.x*256 + threadIdx.x;
    if (j >= 512) return;
    const float* bv = bb.p[z] + 2*DD;
    const float* bo = bb.p[z] + 3*DD;
    const float* Wo = wb.p[z] + (size_t)3*DD*DD;
    float s = bo[j];
    for (int m=0;m<512;m++) s += bv[m]*Wo[(size_t)m*512 + j];
    bvo[z*DD + j] = s;
}

// ---------------- batched split+transpose of 8 512x512 mats (Wq, Wk; bf16) ----------------
__global__ void split512b_k(P4 wb, bf16* __restrict__ oh, bf16* __restrict__ ol){
    __shared__ float t[32][33];
    int z = blockIdx.z;
    const float* W = (z < 4) ? wb.p[z] : wb.p[z-4] + (size_t)DD*DD;
    bf16* ohp = oh + (size_t)z*DD*DD;
    bf16* olp = ol + (size_t)z*DD*DD;
    int n0 = blockIdx.x*32, k0 = blockIdx.y*32;
    int x = threadIdx.x, y = threadIdx.y;
    for (int i=y;i<32;i+=8)
        t[i][x] = W[(size_t)(k0+i)*DD + n0 + x];
    __syncthreads();
    for (int i=y;i<32;i+=8){
        float v = t[x][i];
        bf16 h,l; bsplit(v,h,l);
        ohp[(size_t)(n0+i)*DD + k0 + x] = h;
        olp[(size_t)(n0+i)*DD + k0 + x] = l;
    }
}

// ---------------- WVO fp16 split+transpose (4 mats) ----------------
__global__ void splitvoh_k(const float* __restrict__ wvo, hf* __restrict__ oh,
                           hf* __restrict__ ol){
    __shared__ float t[32][33];
    int z = blockIdx.z;
    const float* W = wvo + (size_t)z*DD*DD;
    hf* ohp = oh + (size_t)z*DD*DD;
    hf* olp = ol + (size_t)z*DD*DD;
    int n0 = blockIdx.x*32, k0 = blockIdx.y*32;
    int x = threadIdx.x, y = threadIdx.y;
    for (int i=y;i<32;i+=8)
        t[i][x] = W[(size_t)(k0+i)*DD + n0 + x];
    __syncthreads();
    for (int i=y;i<32;i+=8){
        float v = t[x][i];
        hf h,l; hsplit(v,h,l);
        ohp[(size_t)(n0+i)*DD + k0 + x] = h;
        olp[(size_t)(n0+i)*DD + k0 + x] = l;
    }
}

// ---------------- FF weight fp16 split+transpose ----------------
__global__ void splitffh_k(P3 Wl, hf* __restrict__ oh, hf* __restrict__ ol,
                           int Kd, int Nd){
    __shared__ float t[32][33];
    int z = blockIdx.z;
    const float* W = Wl.p[z];
    hf* ohp = oh + (size_t)z*Kd*Nd;
    hf* olp = ol + (size_t)z*Kd*Nd;
    int n0 = blockIdx.x*32, k0 = blockIdx.y*32;
    int x = threadIdx.x, y = threadIdx.y;
    for (int i=y;i<32;i+=8)
        t[i][x] = W[(size_t)(k0+i)*Nd + n0 + x];
    __syncthreads();
    for (int i=y;i<32;i+=8){
        float v = t[x][i];
        hf h,l; hsplit(v,h,l);
        ohp[(size_t)(n0+i)*Kd + k0 + x] = h;
        olp[(size_t)(n0+i)*Kd + k0 + x] = l;
    }
}

// ---------------- roll & weight + residual (float4) ----------------
__global__ void roll_res_k(const float* __restrict__ P, const float* __restrict__ w,
                           const int* __restrict__ d, const float* __restrict__ res,
                           float* __restrict__ out){
    int idx = blockIdx.x*256 + threadIdx.x;
    if (idx >= BLD/4) return;
    int c4 = idx & 127;
    int t = (idx >> 7) & (LL-1);
    int b = idx >> 17;
    float4 s = __ldg(&((const float4*)res)[idx]);
#pragma unroll
    for (int i=0;i<TOPK;i++){
        int   dl = __ldg(&d[b*8+i]);
        float wi = __ldg(&w[b*8+i]);
        int tt = (t + dl) & (LL-1);
        float4 v = __ldg(&((const float4*)P)[((size_t)(b*LL + tt) << 7) + c4]);
        s.x += wi*v.x; s.y += wi*v.y; s.z += wi*v.z; s.w += wi*v.w;
    }
    ((float4*)out)[idx] = s;
}

// ---------------- series decomposition (moving mean k=25) ----------------
__global__ void decomp_k(const float* __restrict__ x, float* __restrict__ seas,
                         float* __restrict__ trend, int C, int mode,
                         bf16* __restrict__ oh, bf16* __restrict__ ol,
                         hf* __restrict__ of){
    int b = blockIdx.z;
    int c = blockIdx.x*blockDim.x + threadIdx.x;
    if (c >= C) return;
    int l0 = blockIdx.y * 128;
    const float* xb = x + (size_t)b*LL*C + c;
    float sum = 0.f;
    for (int j=l0-12;j<=l0+12;j++){
        int jj = min(max(j,0), LL-1);
        sum += xb[(size_t)jj*C];
    }
    for (int l=l0; l<l0+128; l++){
        float m = sum * (1.0f/25.0f);
        size_t o = (size_t)b*LL*C + (size_t)l*C + c;
        float sv = x[o] - m;
        seas[o] = sv;
        if (oh){
            bf16 h,lo; bsplit(sv,h,lo); oh[o]=h; ol[o]=lo;
            of[o] = __float2half(sv);
        }
        if (mode==1) trend[o] = m;
        else if (mode==2) trend[o] += m;
        int ja = min(l+13, LL-1), jr = max(l-12, 0);
        sum += xb[(size_t)ja*C] - xb[(size_t)jr*C];
    }
}

// ---------------- layernorm over feature dim ----------------
__global__ void ln_k(const float* __restrict__ x, const float* __restrict__ w,
                     const float* __restrict__ bv, float* __restrict__ y){
    __shared__ float red[256];
    int row = blockIdx.x, tid = threadIdx.x;
    const float* xr = x + (size_t)row*DD;
    float v0 = xr[tid], v1 = xr[tid+256];
    red[tid] = v0+v1; __syncthreads();
    for (int o=128;o;o>>=1){ if (tid<o) red[tid]+=red[tid+o]; __syncthreads(); }
    float mu = red[0]*(1.0f/512.0f);
    __syncthreads();
    float d0=v0-mu, d1=v1-mu;
    red[tid] = d0*d0+d1*d1; __syncthreads();
    for (int o=128;o;o>>=1){ if (tid<o) red[tid]+=red[tid+o]; __syncthreads(); }
    float rstd = rsqrtf(red[0]*(1.0f/512.0f) + 1e-5f);
    y[(size_t)row*DD + tid]     = d0*rstd*w[tid]     + bv[tid];
    y[(size_t)row*DD + tid+256] = d1*rstd*w[tid+256] + bv[tid+256];
}

// ---------------- column (time) mean ----------------
__global__ void zero_k(float* p, int n){
    int i = blockIdx.x*blockDim.x + threadIdx.x;
    if (i < n) p[i] = 0.0f;
}
__global__ void colsum_k(const float* __restrict__ x, float* __restrict__ cm){
    int b = blockIdx.z;
    int c = blockIdx.x*256 + threadIdx.x;
    int l0 = blockIdx.y*128;
    float s=0.f;
    for (int l=l0;l<l0+128;l++) s += x[((size_t)b*LL + l)*DD + c];
    atomicAdd(&cm[b*DD + c], s);
}
__global__ void colsub_k(const float* __restrict__ x, const float* __restrict__ cm,
                         float* __restrict__ y, bf16* __restrict__ oh, bf16* __restrict__ ol,
                         hf* __restrict__ of){
    int idx = blockIdx.x*256 + threadIdx.x;
    if (idx >= BLD/4) return;
    int c4 = idx & 127;
    int b = idx >> 17;
    float4 xv = __ldg(&((const float4*)x)[idx]);
    float4 cv = __ldg(&((const float4*)cm)[b*128 + c4]);
    float4 v;
    v.x = xv.x - cv.x*(1.0f/1024.0f);
    v.y = xv.y - cv.y*(1.0f/1024.0f);
    v.z = xv.z - cv.z*(1.0f/1024.0f);
    v.w = xv.w - cv.w*(1.0f/1024.0f);
    ((float4*)y)[idx] = v;
    if (oh){
        bf16 h0,l0,h1,l1,h2,l2,h3,l3;
        bsplit(v.x,h0,l0); bsplit(v.y,h1,l1); bsplit(v.z,h2,l2); bsplit(v.w,h3,l3);
        __nv_bfloat162* oh2 = (__nv_bfloat162*)oh;
        __nv_bfloat162* ol2 = (__nv_bfloat162*)ol;
        __nv_bfloat162 a,bb2;
        a.x=h0; a.y=h1; bb2.x=h2; bb2.y=h3;
        oh2[2*idx]=a; oh2[2*idx+1]=bb2;
        a.x=l0; a.y=l1; bb2.x=l2; bb2.y=l3;
        ol2[2*idx]=a; ol2[2*idx+1]=bb2;
        __half2* of2 = (__half2*)of;
        __half2 f0; f0.x=__float2half(v.x); f0.y=__float2half(v.y);
        __half2 f1; f1.x=__float2half(v.z); f1.y=__float2half(v.w);
        of2[2*idx]=f0; of2[2*idx+1]=f1;
    }
}

// ---------------- embedding (weight-register reuse, 8 l per thread) ----------------
__global__ void embed_k(const float* __restrict__ x, const float* __restrict__ mark,
                        const float* __restrict__ Wtok, const float* __restrict__ Wtem,
                        float* __restrict__ out, bf16* __restrict__ oh, bf16* __restrict__ ol,
                        hf* __restrict__ of){
    int d = blockIdx.x*256 + threadIdx.x;
    int b = blockIdx.z;
    int l0 = blockIdx.y*8;
    float w[21], wt[4];
#pragma unroll
    for (int i=0;i<21;i++) w[i] = __ldg(&Wtok[(size_t)i*DD + d]);
#pragma unroll
    for (int m=0;m<MK;m++) wt[m] = __ldg(&Wtem[(size_t)m*DD + d]);
#pragma unroll
    for (int i=0;i<8;i++){
        int l = l0 + i;
        int lm = (l + LL - 1) & (LL-1), lp = (l + 1) & (LL-1);
        const float* x0 = x + ((size_t)b*LL + lm)*CIN;
        const float* x1 = x + ((size_t)b*LL + l )*CIN;
        const float* x2 = x + ((size_t)b*LL + lp)*CIN;
        float s = 0.f;
#pragma unroll
        for (int c=0;c<CIN;c++){
            s += x0[c]*w[c];
            s += x1[c]*w[7+c];
            s += x2[c]*w[14+c];
        }
        const float* mk = mark + ((size_t)b*LL + l)*MK;
#pragma unroll
        for (int m=0;m<MK;m++) s += mk[m]*wt[m];
        size_t o = ((size_t)b*LL + l)*DD + d;
        out[o] = s;
        bf16 h,lo; bsplit(s,h,lo); oh[o]=h; ol[o]=lo;
        of[o] = __float2half(s);
    }
}

// ---------------- mean of x_enc over time ----------------
__global__ void meanenc_k(const float* __restrict__ x, float* __restrict__ m){
    __shared__ float red[256];
    int b = blockIdx.x / CIN, c = blockIdx.x % CIN;
    int tid = threadIdx.x;
    float s=0.f;
    for (int l=tid;l<LL;l+=256) s += x[((size_t)b*LL + l)*CIN + c];
    red[tid]=s; __syncthreads();
    for (int o=128;o;o>>=1){ if (tid<o) red[tid]+=red[tid+o]; __syncthreads(); }
    if (tid==0) m[blockIdx.x] = red[0]*(1.0f/1024.0f);
}

__global__ void decinit_k(const float* __restrict__ sx, const float* __restrict__ tx,
                          const float* __restrict__ menc, float* __restrict__ seas,
                          float* __restrict__ trend){
    int idx = blockIdx.x*256 + threadIdx.x;
    if (idx >= BL7) return;
    int c = idx % CIN;
    int l = (idx / CIN) % LL;
    int b = idx / (CIN*LL);
    if (l < 512){
        size_t src = ((size_t)b*LL + 512 + l)*CIN + c;
        seas[idx]  = sx[src];
        trend[idx] = tx[src];
    } else {
        seas[idx]  = 0.f;
        trend[idx] = menc[b*CIN + c];
    }
}

__global__ void trendconv_k(const float* __restrict__ t123, const float* __restrict__ Wt,
                            float* __restrict__ trend){
    int idx = blockIdx.x*256 + threadIdx.x;
    if (idx >= BL7) return;
    int c = idx % CIN;
    int l = (idx / CIN) % LL;
    int b = idx / (CIN*LL);
    int lm = (l + LL - 1) & (LL-1), lp = (l + 1) & (LL-1);
    const float* r0 = t123 + ((size_t)b*LL + lm)*DD;
    const float* r1 = t123 + ((size_t)b*LL + l )*DD;
    const float* r2 = t123 + ((size_t)b*LL + lp)*DD;
    float s = 0.f;
    for (int d=0; d<DD; d++){
        s += r0[d]*__ldg(&Wt[(0*DD+d)*CIN + c]);
        s += r1[d]*__ldg(&Wt[(1*DD+d)*CIN + c]);
        s += r2[d]*__ldg(&Wt[(2*DD+d)*CIN + c]);
    }
    trend[idx] += s;
}

__global__ void final_k(const float* __restrict__ dec, const float* __restrict__ projW,
                        const float* __restrict__ projb, const float* __restrict__ trend,
                        float* __restrict__ out){
    int idx = blockIdx.x*256 + threadIdx.x;
    if (idx >= BB*512*CIN) return;
    int c = idx % CIN;
    int lp = (idx / CIN) % 512;
    int b = idx / (512*CIN);
    int l = 512 + lp;
    const float* r = dec + ((size_t)b*LL + l)*DD;
    float s = projb[c];
    for (int d=0; d<DD; d++) s += r[d]*__ldg(&projW[d*CIN + c]);
    out[idx] = trend[((size_t)b*LL + l)*CIN + c] + s;
}

// ---------------- host orchestration ----------------
static void gemm_qk(const bf16* ah, const bf16* al, const bf16* bh, const bf16* bl,
                    const float* bias, bf16* Ch, bf16* Cl){
    dim3 g(DD/128, MROWS/128);
    gemm_mma_k<<<g, 512, GEMM_SMEM>>>(ah, al, bh, bl, bias, Ch, Cl, DD);
}
static void gemm2h(const hf* a, const hf* bh, const hf* bl,
                   const float* bias, const float* res,
                   float* C, hf* Cf, int N, int K, int gelu){
    dim3 g(N/128, MROWS/128);
    gemm2h_k<<<g, 512, GEMM2_SMEM>>>(a, bh, bl, bias, res, C, Cf, N, K, gelu);
}

static void run_attn(int ai, const float* res,
                     const bf16* xqh, const bf16* xql,
                     const bf16* xkvh, const bf16* xkvl, const hf* xkvf,
                     const float* bias, float* outb, float* Pv,
                     bf16* QH, bf16* QL, bf16* KH, bf16* KL,
                     float* G, float* CP, float* wbuf, int* dbuf,
                     bf16* MH, bf16* ML, hf* VH, hf* VL, float* BVO4){
    gemm_qk(xqh, xql,  MH + (size_t)ai*DD*DD,     ML + (size_t)ai*DD*DD,
            bias, QH, QL);
    gemm_qk(xkvh, xkvl, MH + (size_t)(4+ai)*DD*DD, ML + (size_t)(4+ai)*DD*DD,
            bias + DD, KH, KL);
    gemm2h(xkvf, VH + (size_t)ai*DD*DD, VL + (size_t)ai*DD*DD,
           BVO4 + ai*DD, nullptr, Pv, nullptr, DD, DD, 0);
    corrg_k<<<dim3(LL/128, LL/128, BB), 512, GEMM_SMEM>>>(QH, QL, KH, KL, G);
    diagsum_k<<<dim3(32, BB), 256>>>(G, CP);
    corr_topk_k<<<BB, 256>>>(CP, wbuf, dbuf);
    roll_res_k<<<(BLD/4)/256, 256>>>(Pv, wbuf, dbuf, res, outb);
}

extern "C" void kernel_launch(void* const* d_in, const int* in_sizes, int n_in,
                              void* d_out, int out_size){
    const float* x_enc      = (const float*)d_in[0];
    const float* x_mark_enc = (const float*)d_in[1];
    const float* x_mark_dec = (const float*)d_in[3];
    const float* W_enc_tok  = (const float*)d_in[4];
    const float* W_enc_tem  = (const float*)d_in[5];
    const float* W_dec_tok  = (const float*)d_in[6];
    const float* W_dec_tem  = (const float*)d_in[7];
    const float* enc_attn_W = (const float*)d_in[8];
    const float* enc_attn_b = (const float*)d_in[9];
    const float* enc_ff1    = (const float*)d_in[10];
    const float* enc_ff2    = (const float*)d_in[11];
    const float* enc_ln_w   = (const float*)d_in[12];
    const float* enc_ln_b   = (const float*)d_in[13];
    const float* dec_self_W = (const float*)d_in[14];
    const float* dec_self_b = (const float*)d_in[15];
    const float* dec_cross_W= (const float*)d_in[16];
    const float* dec_cross_b= (const float*)d_in[17];
    const float* dec_ff1    = (const float*)d_in[18];
    const float* dec_ff2    = (const float*)d_in[19];
    const float* dec_trend_W= (const float*)d_in[20];
    const float* dec_ln_w   = (const float*)d_in[21];
    const float* dec_ln_b   = (const float*)d_in[22];
    const float* proj_W     = (const float*)d_in[23];
    const float* proj_b     = (const float*)d_in[24];
    float* out = (float*)d_out;

    cudaFuncSetAttribute(gemm_mma_k, cudaFuncAttributeMaxDynamicSharedMemorySize, GEMM_SMEM);
    cudaFuncSetAttribute(corrg_k,   cudaFuncAttributeMaxDynamicSharedMemorySize, GEMM_SMEM);
    cudaFuncSetAttribute(gemm2h_k,  cudaFuncAttributeMaxDynamicSharedMemorySize, GEMM2_SMEM);

    void *pA,*pB,*pv,*penc,*pt123,*pG,*pcp,*pcm,*pw,*pd;
    void *psx,*ptx,*pseas,*ptrd,*pmenc,*pwvo,*pbvo;
    void *ps1h,*ps1l,*pech,*pecl,*pqh,*pql,*pkh,*pkl;
    void *pmh,*pml,*pvh,*pvl,*pf1h,*pf1l,*pf2h,*pf2l,*px1f,*pecf,*px2f;
    cudaGetSymbolAddress(&pA, g_A);       cudaGetSymbolAddress(&pB, g_Bf);
    cudaGetSymbolAddress(&pv, g_v);       cudaGetSymbolAddress(&penc, g_enc);
    cudaGetSymbolAddress(&pt123, g_t123);
    cudaGetSymbolAddress(&pG, g_G);       cudaGetSymbolAddress(&pcp, g_cp);
    cudaGetSymbolAddress(&pcm, g_cm);
    cudaGetSymbolAddress(&pw, g_w);       cudaGetSymbolAddress(&pd, g_dly);
    cudaGetSymbolAddress(&psx, g_sx);     cudaGetSymbolAddress(&ptx, g_tx);
    cudaGetSymbolAddress(&pseas, g_seas); cudaGetSymbolAddress(&ptrd, g_trd);
    cudaGetSymbolAddress(&pmenc, g_menc);
    cudaGetSymbolAddress(&pwvo, g_wvo4);  cudaGetSymbolAddress(&pbvo, g_bvo4);
    cudaGetSymbolAddress(&ps1h, g_s1h);   cudaGetSymbolAddress(&ps1l, g_s1l);
    cudaGetSymbolAddress(&pech, g_ench);  cudaGetSymbolAddress(&pecl, g_encl);
    cudaGetSymbolAddress(&pqh, g_qh);     cudaGetSymbolAddress(&pql, g_ql);
    cudaGetSymbolAddress(&pkh, g_kh);     cudaGetSymbolAddress(&pkl, g_kl);
    cudaGetSymbolAddress(&pmh, g_mh);     cudaGetSymbolAddress(&pml, g_ml);
    cudaGetSymbolAddress(&pvh, g_vh);     cudaGetSymbolAddress(&pvl, g_vl);
    cudaGetSymbolAddress(&pf1h, g_f1h);   cudaGetSymbolAddress(&pf1l, g_f1l);
    cudaGetSymbolAddress(&pf2h, g_f2h);   cudaGetSymbolAddress(&pf2l, g_f2l);
    cudaGetSymbolAddress(&px1f, g_x1f);   cudaGetSymbolAddress(&pecf, g_ecf);
    cudaGetSymbolAddress(&px2f, g_x2f);

    float *A_=(float*)pA, *B_=(float*)pB, *V=(float*)pv;
    float *ENC=(float*)penc, *T123=(float*)pt123, *G=(float*)pG, *CP=(float*)pcp;
    float *CM=(float*)pcm, *WW=(float*)pw; int *DL=(int*)pd;
    float *SX=(float*)psx, *TX=(float*)ptx, *SEAS=(float*)pseas, *TRD=(float*)ptrd, *MENC=(float*)pmenc;
    float *WVO4=(float*)pwvo, *BVO4=(float*)pbvo;
    bf16 *S1H=(bf16*)ps1h, *S1L=(bf16*)ps1l, *ECH=(bf16*)pech, *ECL=(bf16*)pecl;
    bf16 *QH=(bf16*)pqh, *QL=(bf16*)pql, *KH=(bf16*)pkh, *KL=(bf16*)pkl;
    bf16 *MH=(bf16*)pmh, *ML=(bf16*)pml;
    hf *VH=(hf*)pvh, *VL=(hf*)pvl;
    hf *F1H=(hf*)pf1h, *F1L=(hf*)pf1l, *F2H=(hf*)pf2h, *F2L=(hf*)pf2l;
    hf *X1F=(hf*)px1f, *ECF=(hf*)pecf, *X2F=(hf*)px2f;

    // ---- batched weight prep ----
    P4 wb; wb.p[0]=enc_attn_W; wb.p[1]=enc_attn_W + (size_t)4*DD*DD;
           wb.p[2]=dec_self_W; wb.p[3]=dec_cross_W;
    P4 bb; bb.p[0]=enc_attn_b; bb.p[1]=enc_attn_b + 4*DD;
           bb.p[2]=dec_self_b; bb.p[3]=dec_cross_b;
    mmvo_b_k<<<dim3(16,16,4), dim3(32,8)>>>(wb, WVO4);
    biasvo_b_k<<<dim3(2,4), 256>>>(bb, wb, BVO4);
    split512b_k<<<dim3(16,16,8), dim3(32,8)>>>(wb, MH, ML);
    splitvoh_k<<<dim3(16,16,4), dim3(32,8)>>>(WVO4, VH, VL);
    P3 f1; f1.p[0]=enc_ff1; f1.p[1]=enc_ff1 + (size_t)DD*DFF; f1.p[2]=dec_ff1;
    P3 f2; f2.p[0]=enc_ff2; f2.p[1]=enc_ff2 + (size_t)DFF*DD; f2.p[2]=dec_ff2;
    splitffh_k<<<dim3(64,16,3), dim3(32,8)>>>(f1, F1H, F1L, DD, DFF);
    splitffh_k<<<dim3(16,64,3), dim3(32,8)>>>(f2, F2H, F2L, DFF, DD);

    // ---- decoder init tensors (from x_enc) ----
    decomp_k<<<dim3(1,8,BB), 32>>>(x_enc, SX, TX, CIN, 1, nullptr, nullptr, nullptr);
    meanenc_k<<<BB*CIN, 256>>>(x_enc, MENC);
    decinit_k<<<(BL7+255)/256, 256>>>(SX, TX, MENC, SEAS, TRD);

    // ---- encoder ----
    embed_k<<<dim3(2, LL/8, BB), 256>>>(x_enc, x_mark_enc, W_enc_tok, W_enc_tem,
                                        A_, S1H, S1L, X1F);
    for (int l=0; l<2; l++){
        run_attn(l, A_, S1H, S1L, S1H, S1L, X1F,
                 enc_attn_b + (size_t)l*4*DD,
                 B_, V, QH, QL, KH, KL, G, CP, WW, DL, MH, ML, VH, VL, BVO4);
        decomp_k<<<dim3(2,8,BB), 256>>>(B_, A_, nullptr, DD, 0, S1H, S1L, X1F);
        gemm2h(X1F, F1H + (size_t)l*DD*DFF, F1L + (size_t)l*DD*DFF,
               nullptr, nullptr, nullptr, X2F, DFF, DD, 1);
        gemm2h(X2F, F2H + (size_t)l*DFF*DD, F2L + (size_t)l*DFF*DD,
               nullptr, A_, B_, nullptr, DD, DFF, 0);
        decomp_k<<<dim3(2,8,BB), 256>>>(B_, A_, nullptr, DD, 0, S1H, S1L, X1F);
    }
    ln_k<<<MROWS, 256>>>(A_, enc_ln_w, enc_ln_b, B_);
    zero_k<<<(BB*DD+255)/256, 256>>>(CM, BB*DD);
    colsum_k<<<dim3(2,8,BB), 256>>>(B_, CM);
    colsub_k<<<(BLD/4)/256, 256>>>(B_, CM, ENC, ECH, ECL, ECF);

    // ---- decoder ----
    embed_k<<<dim3(2, LL/8, BB), 256>>>(SEAS, x_mark_dec, W_dec_tok, W_dec_tem,
                                        A_, S1H, S1L, X1F);
    run_attn(2, A_, S1H, S1L, S1H, S1L, X1F, dec_self_b,
             B_, V, QH, QL, KH, KL, G, CP, WW, DL, MH, ML, VH, VL, BVO4);
    decomp_k<<<dim3(2,8,BB), 256>>>(B_, A_, T123, DD, 1, S1H, S1L, X1F);
    run_attn(3, A_, S1H, S1L, ECH, ECL, ECF, dec_cross_b,
             B_, V, QH, QL, KH, KL, G, CP, WW, DL, MH, ML, VH, VL, BVO4);
    decomp_k<<<dim3(2,8,BB), 256>>>(B_, A_, T123, DD, 2, S1H, S1L, X1F);
    gemm2h(X1F, F1H + (size_t)2*DD*DFF, F1L + (size_t)2*DD*DFF,
           nullptr, nullptr, nullptr, X2F, DFF, DD, 1);
    gemm2h(X2F, F2H + (size_t)2*DFF*DD, F2L + (size_t)2*DFF*DD,
           nullptr, A_, B_, nullptr, DD, DFF, 0);
    decomp_k<<<dim3(2,8,BB), 256>>>(B_, A_, T123, DD, 2, S1H, S1L, X1F);
    trendconv_k<<<(BL7+255)/256, 256>>>(T123, dec_trend_W, TRD);
    ln_k<<<MROWS, 256>>>(A_, dec_ln_w, dec_ln_b, B_);
    zero_k<<<(BB*DD+255)/256, 256>>>(CM, BB*DD);
    colsum_k<<<dim3(2,8,BB), 256>>>(B_, CM);
    colsub_k<<<(BLD/4)/256, 256>>>(B_, CM, A_, nullptr, nullptr, nullptr);
    final_k<<<(BB*512*CIN+255)/256, 256>>>(A_, proj_W, proj_b, TRD, out);
}